// round 14
// baseline (speedup 1.0000x reference)
#include <cuda_runtime.h>
#include <cuda_bf16.h>
#include <math.h>

// out[i] = mean_{p != i} ( tanh( [x_i, x_p] @ W1 + b1 ) @ W2 + b2 )
// A = x@W1[:64] + b1, B = x@W1[64:]
// S[i,h] = sum_p tanh(A[i,h]+B[p,h]) via separable 2D Chebyshev:
//   tanh(a+b) ~= sum_{j,k<=DEG} C_jk T_j(a/D) T_k(b/D)
//   M_k[h] = sum_p T_k(B~[p,h]);  R_j[h] = sum_k C_jk M_k[h]
//   S[i,h] = sum_j T_j(A~[i,h]) R_j[h]
// out[i] = ((S[i] - tanh(A[i]+B[i])) / 1023) @ W2 + b2
// Degree calibration (measured): truncation(d) ~ 7e-9 * 1.36^(48-d) at D=5;
// D=4 improves decay ~1.24x/deg -> DEG=24 @ D=4 gives ~2e-6, 500x under gate.

#define N_E    1024
#define N_IN   64
#define HIDDEN 128
#define OUTD   64

#define DEG    24
#define NC     (DEG + 1)        // 25
#define NQ     48
#define DDOM   4.0f

#define TI1    4                // i-rows per block, phase 1
#define FSPLIT 4
#define FPT    (N_IN / FSPLIT)  // 16
#define TI4    2                // i-rows per block, main kernel
#define PC3    2                // p-range split in k3

// Scratch (device globals — no runtime allocation allowed)
__device__ float g_A[N_E * HIDDEN];
__device__ float g_B[N_E * HIDDEN];
__device__ float g_F[NQ * NQ];
__device__ float g_cosT[NC * NQ];
__device__ float g_C[NC * NC];
__device__ float g_Rp[PC3][NC * HIDDEN];   // partial R per p-half

__device__ __forceinline__ float tanh_fast(float x) {
    float y;
    asm("tanh.approx.f32 %0, %1;" : "=f"(y) : "f"(x));
    return y;
}

// ---------------------------------------------------------------------------
// K1: phase1 GEMMs (blocks [0,256)) + node tables (blocks 256, 257).
// ---------------------------------------------------------------------------
__global__ void __launch_bounds__(FSPLIT * HIDDEN) k1_phase1_tables(
    const float* __restrict__ x, const float* __restrict__ W1,
    const float* __restrict__ b1)
{
    const int t = threadIdx.x;

    if (blockIdx.x == (N_E / TI1)) {
        // cosT[j*NQ+p] = cos(j*theta_p) via double recurrence.
        if (t < NQ) {
            const double th = (t + 0.5) * (3.14159265358979323846 / NQ);
            const double c1 = cos(th);
            double cm = 1.0, cc = c1;
            g_cosT[0 * NQ + t] = 1.0f;
            g_cosT[1 * NQ + t] = (float)c1;
            for (int j = 2; j < NC; j++) {
                const double cn = 2.0 * c1 * cc - cm;
                g_cosT[j * NQ + t] = (float)cn;
                cm = cc; cc = cn;
            }
        }
        return;
    }
    if (blockIdx.x == (N_E / TI1) + 1) {
        // F[p*NQ+q] = tanh(D*(x_p + x_q))
        __shared__ float xn[NQ];
        if (t < NQ) {
            const double th = (t + 0.5) * (3.14159265358979323846 / NQ);
            xn[t] = (float)cos(th);
        }
        __syncthreads();
        for (int idx = t; idx < NQ * NQ; idx += FSPLIT * HIDDEN) {
            const int p = idx / NQ, q = idx % NQ;
            g_F[idx] = tanhf(DDOM * (xn[p] + xn[q]));
        }
        return;
    }

    const int h  = t & (HIDDEN - 1);
    const int fg = t >> 7;
    const int i0 = blockIdx.x * TI1;

    __shared__ float xs[TI1][N_IN];                      // 1 KB
    __shared__ float red[FSPLIT][2][TI1][HIDDEN];        // 16 KB

    if (t < TI1 * N_IN) xs[t >> 6][t & 63] = x[i0 * N_IN + t];
    __syncthreads();

    float a[TI1], b[TI1];
    #pragma unroll
    for (int k = 0; k < TI1; k++) { a[k] = 0.0f; b[k] = 0.0f; }

    const int fbase = fg * FPT;
    #pragma unroll
    for (int ff = 0; ff < FPT; ff++) {
        const int f = fbase + ff;
        const float wa = W1[f * HIDDEN + h];
        const float wb = W1[(N_IN + f) * HIDDEN + h];
        #pragma unroll
        for (int k = 0; k < TI1; k++) {
            const float xv = xs[k][f];
            a[k] = fmaf(xv, wa, a[k]);
            b[k] = fmaf(xv, wb, b[k]);
        }
    }

    #pragma unroll
    for (int k = 0; k < TI1; k++) {
        red[fg][0][k][h] = a[k];
        red[fg][1][k][h] = b[k];
    }
    __syncthreads();

    if (fg == 0) {
        const float bb = b1[h];
        #pragma unroll
        for (int k = 0; k < TI1; k++) {
            float av = a[k] + red[1][0][k][h] + red[2][0][k][h] + red[3][0][k][h];
            float bv = b[k] + red[1][1][k][h] + red[2][1][k][h] + red[3][1][k][h];
            g_A[(i0 + k) * HIDDEN + h] = av + bb;
            g_B[(i0 + k) * HIDDEN + h] = bv;
        }
    }
}

// ---------------------------------------------------------------------------
// K2: separable 2D DCT -> C_jk. One block per j (NC x NQ threads).
// Double accumulation, chains split for DFMA latency.
// ---------------------------------------------------------------------------
__global__ void __launch_bounds__(NQ) k2_dct()
{
    const int j = blockIdx.x;
    const int t = threadIdx.x;

    __shared__ double Gq[NQ];

    double g0 = 0.0, g1 = 0.0, g2 = 0.0, g3 = 0.0;
    #pragma unroll
    for (int p = 0; p < NQ; p += 4) {
        g0 += (double)g_F[(p + 0) * NQ + t] * (double)g_cosT[j * NQ + p + 0];
        g1 += (double)g_F[(p + 1) * NQ + t] * (double)g_cosT[j * NQ + p + 1];
        g2 += (double)g_F[(p + 2) * NQ + t] * (double)g_cosT[j * NQ + p + 2];
        g3 += (double)g_F[(p + 3) * NQ + t] * (double)g_cosT[j * NQ + p + 3];
    }
    Gq[t] = (g0 + g1) + (g2 + g3);
    __syncthreads();

    if (t < NC) {
        double c0 = 0.0, c1 = 0.0;
        #pragma unroll
        for (int q = 0; q < NQ; q += 2) {
            c0 += Gq[q]     * (double)g_cosT[t * NQ + q];
            c1 += Gq[q + 1] * (double)g_cosT[t * NQ + q + 1];
        }
        const double wj = (j == 0) ? 1.0 : 2.0;
        const double wk = (t == 0) ? 1.0 : 2.0;
        g_C[j * NC + t] = (float)((c0 + c1) * wj * wk / ((double)NQ * NQ));
    }
}

// ---------------------------------------------------------------------------
// K3: moments + reduce, p-range split 2 ways (256 blocks, full-chip coverage).
// Block (h, pc): M_k^pc[h] = sum_{p in half pc} T_k(B~[p,h]);
// R^pc_j[h] = sum_k C_jk M^pc_k[h] (linear, halves add in K4).
// 512 threads, 1 p per thread, warp-shuffle reduce.
// ---------------------------------------------------------------------------
__global__ void __launch_bounds__(512) k3_moments()
{
    const int h    = blockIdx.x >> 1;
    const int pc   = blockIdx.x & 1;
    const int t    = threadIdx.x;
    const int lane = t & 31;
    const int wid  = t >> 5;              // 16 warps
    const float invD = 1.0f / DDOM;

    float m[NC];
    {
        const int p = pc * 512 + t;
        float xv = g_B[p * HIDDEN + h] * invD;
        xv = fminf(fmaxf(xv, -1.0f), 1.0f);
        float tp = 1.0f, tc = xv;
        m[0] = 1.0f;
        m[1] = xv;
        const float x2 = 2.0f * xv;
        #pragma unroll
        for (int k = 2; k < NC; k++) {
            const float tn = fmaf(x2, tc, -tp);
            m[k] = tn;
            tp = tc; tc = tn;
        }
    }

    __shared__ float warp_red[16][NC];
    __shared__ float Msh[NC];

    #pragma unroll
    for (int k = 0; k < NC; k++) {
        float v = m[k];
        v += __shfl_xor_sync(0xffffffff, v, 16);
        v += __shfl_xor_sync(0xffffffff, v, 8);
        v += __shfl_xor_sync(0xffffffff, v, 4);
        v += __shfl_xor_sync(0xffffffff, v, 2);
        v += __shfl_xor_sync(0xffffffff, v, 1);
        if (lane == 0) warp_red[wid][k] = v;
    }
    __syncthreads();

    if (t < NC) {
        float s = 0.0f;
        #pragma unroll
        for (int w = 0; w < 16; w++) s += warp_red[w][t];
        Msh[t] = s;
    }
    __syncthreads();

    if (t < NC) {
        float r0 = 0.0f, r1 = 0.0f;
        #pragma unroll
        for (int k = 0; k < NC - 1; k += 2) {
            r0 = fmaf(g_C[t * NC + k],     Msh[k],     r0);
            r1 = fmaf(g_C[t * NC + k + 1], Msh[k + 1], r1);
        }
        r0 = fmaf(g_C[t * NC + NC - 1], Msh[NC - 1], r0);
        g_Rp[pc][t * HIDDEN + h] = r0 + r1;
    }
}

// ---------------------------------------------------------------------------
// K4: fused main. 512 blocks x 256 threads; block covers 2 i-rows.
// All NC R-coefficients preloaded into registers (no memory ops inside the
// recurrence — kills the long-scoreboard stalls seen at L1=23%).
// Then self-term + W2 GEMV in-block.
// ---------------------------------------------------------------------------
__global__ void __launch_bounds__(2 * HIDDEN) k4_main(
    const float* __restrict__ W2, const float* __restrict__ b2,
    float* __restrict__ out)
{
    const int t  = threadIdx.x;
    const int h  = t & (HIDDEN - 1);
    const int ig = t >> 7;                // 0..1: which i-row
    const int i0 = blockIdx.x * TI4;
    const int i  = i0 + ig;
    const float invD = 1.0f / DDOM;

    __shared__ float s2[HIDDEN][TI4];     // 1 KB
    __shared__ float po[2][TI4][OUTD];    // 2 KB

    // Preload all R into registers (sum of the two p-half partials).
    float rj[NC];
    #pragma unroll
    for (int j = 0; j < NC; j++)
        rj[j] = __ldg(&g_Rp[0][j * HIDDEN + h]) + __ldg(&g_Rp[1][j * HIDDEN + h]);

    // Chebyshev evaluation: one (i,h) per thread, pure-FMA chain.
    const float araw = g_A[i * HIDDEN + h];
    float a = araw * invD;
    a = fminf(fmaxf(a, -1.0f), 1.0f);
    const float x2 = 2.0f * a;
    float tp = 1.0f, tc = a;
    float s = fmaf(rj[1], a, rj[0]);

    #pragma unroll
    for (int j = 2; j < NC; j++) {
        const float tn = fmaf(x2, tc, -tp);
        s = fmaf(rj[j], tn, s);
        tp = tc; tc = tn;
    }

    // self term + scale
    const float self_t = tanh_fast(araw + g_B[i * HIDDEN + h]);
    s2[h][ig] = (s - self_t) * (1.0f / (float)(N_E - 1));
    __syncthreads();

    // GEMV through W2: 4 groups of 64 threads = (hidden half) x (i-row)
    const int o    = t & (OUTD - 1);
    const int grp  = t >> 6;              // 0..3
    const int il   = grp & 1;             // i-row
    const int half = grp >> 1;            // hidden half

    float acc = 0.0f;
    #pragma unroll 8
    for (int hh = 0; hh < HIDDEN / 2; hh++) {
        const int hid = half * (HIDDEN / 2) + hh;
        acc = fmaf(s2[hid][il], W2[hid * OUTD + o], acc);
    }
    po[half][il][o] = acc;
    __syncthreads();

    if (t < TI4 * OUTD) {
        const int oo = t & (OUTD - 1);
        const int ii = t >> 6;
        out[(i0 + ii) * OUTD + oo] = po[0][ii][oo] + po[1][ii][oo] + b2[oo];
    }
}

// ---------------------------------------------------------------------------
extern "C" void kernel_launch(void* const* d_in, const int* in_sizes, int n_in,
                              void* d_out, int out_size)
{
    // Map inputs by element count (all distinct): x=65536, W1=16384, b1=128,
    // W2=8192, b2=64.
    const float *x = nullptr, *W1 = nullptr, *b1 = nullptr, *W2 = nullptr, *b2 = nullptr;
    for (int i = 0; i < n_in; i++) {
        switch (in_sizes[i]) {
            case N_E * N_IN:          x  = (const float*)d_in[i]; break;
            case 2 * N_IN * HIDDEN:   W1 = (const float*)d_in[i]; break;
            case HIDDEN:              b1 = (const float*)d_in[i]; break;
            case HIDDEN * OUTD:       W2 = (const float*)d_in[i]; break;
            case OUTD:                b2 = (const float*)d_in[i]; break;
            default: break;
        }
    }
    float* out = (float*)d_out;

    k1_phase1_tables<<<N_E / TI1 + 2, FSPLIT * HIDDEN>>>(x, W1, b1);
    k2_dct<<<NC, NQ>>>();
    k3_moments<<<PC3 * HIDDEN, 512>>>();
    k4_main<<<N_E / TI4, 2 * HIDDEN>>>(W2, b2, out);
}

// round 16
// speedup vs baseline: 1.6175x; 1.6175x over previous
#include <cuda_runtime.h>
#include <cuda_bf16.h>
#include <math.h>

// out[i] = mean_{p != i} ( tanh( [x_i, x_p] @ W1 + b1 ) @ W2 + b2 )
// A = x@W1[:64] + b1, B = x@W1[64:]
// S[i,h] = sum_p tanh(A[i,h]+B[p,h]) via separable 2D Chebyshev:
//   tanh(a+b) ~= sum_{j,k<=DEG} C_jk T_j(a/D) T_k(b/D)
//   M_k[h] = sum_p T_k(B~[p,h]);  R_j[h] = sum_k C_jk M_k[h]
//   S[i,h] = sum_j T_j(A~[i,h]) R_j[h]
// out[i] = ((S[i] - tanh(A[i]+B[i])) / 1023) @ W2 + b2
// Calibration: DEG=24 @ D=4 measured rel_err 6.3e-6 (R14) — 160x under gate.
// Structure reverted to R13 (33.3us measured); only degree constants changed.

#define N_E    1024
#define N_IN   64
#define HIDDEN 128
#define OUTD   64

#define DEG    24
#define NC     (DEG + 1)        // 25
#define NQ     48
#define DDOM   4.0f

#define TI1    4                // i-rows per block, phase 1
#define FSPLIT 4
#define FPT    (N_IN / FSPLIT)  // 16
#define TI4    2                // i-rows per block, fused main kernel

// Scratch (device globals — no runtime allocation allowed)
__device__ float g_A[N_E * HIDDEN];
__device__ float g_B[N_E * HIDDEN];
__device__ float g_F[NQ * NQ];
__device__ float g_cosT[NC * NQ];
__device__ float g_C[NC * NC];
__device__ float g_R[NC * HIDDEN];

__device__ __forceinline__ float tanh_fast(float x) {
    float y;
    asm("tanh.approx.f32 %0, %1;" : "=f"(y) : "f"(x));
    return y;
}

// ---------------------------------------------------------------------------
// K1: phase1 GEMMs (blocks [0,256)) + node tables (blocks 256, 257).
// 512 threads/block; f-dim split 4 ways, shared reduce; 4 i-rows per block.
// ---------------------------------------------------------------------------
__global__ void __launch_bounds__(FSPLIT * HIDDEN) k1_phase1_tables(
    const float* __restrict__ x, const float* __restrict__ W1,
    const float* __restrict__ b1)
{
    const int t = threadIdx.x;

    if (blockIdx.x == (N_E / TI1)) {
        // cosT[j*NQ+p] = cos(j*theta_p) via double recurrence (1 double cos).
        if (t < NQ) {
            const double th = (t + 0.5) * (3.14159265358979323846 / NQ);
            const double c1 = cos(th);
            double cm = 1.0, cc = c1;
            g_cosT[0 * NQ + t] = 1.0f;
            g_cosT[1 * NQ + t] = (float)c1;
            for (int j = 2; j < NC; j++) {
                const double cn = 2.0 * c1 * cc - cm;
                g_cosT[j * NQ + t] = (float)cn;
                cm = cc; cc = cn;
            }
        }
        return;
    }
    if (blockIdx.x == (N_E / TI1) + 1) {
        // F[p*NQ+q] = tanh(D*(x_p + x_q))
        __shared__ float xn[NQ];
        if (t < NQ) {
            const double th = (t + 0.5) * (3.14159265358979323846 / NQ);
            xn[t] = (float)cos(th);
        }
        __syncthreads();
        for (int idx = t; idx < NQ * NQ; idx += FSPLIT * HIDDEN) {
            const int p = idx / NQ, q = idx % NQ;
            g_F[idx] = tanhf(DDOM * (xn[p] + xn[q]));
        }
        return;
    }

    const int h  = t & (HIDDEN - 1);
    const int fg = t >> 7;
    const int i0 = blockIdx.x * TI1;

    __shared__ float xs[TI1][N_IN];                      // 1 KB
    __shared__ float red[FSPLIT][2][TI1][HIDDEN];        // 16 KB

    if (t < TI1 * N_IN) xs[t >> 6][t & 63] = x[i0 * N_IN + t];
    __syncthreads();

    float a[TI1], b[TI1];
    #pragma unroll
    for (int k = 0; k < TI1; k++) { a[k] = 0.0f; b[k] = 0.0f; }

    const int fbase = fg * FPT;
    #pragma unroll
    for (int ff = 0; ff < FPT; ff++) {
        const int f = fbase + ff;
        const float wa = W1[f * HIDDEN + h];
        const float wb = W1[(N_IN + f) * HIDDEN + h];
        #pragma unroll
        for (int k = 0; k < TI1; k++) {
            const float xv = xs[k][f];
            a[k] = fmaf(xv, wa, a[k]);
            b[k] = fmaf(xv, wb, b[k]);
        }
    }

    #pragma unroll
    for (int k = 0; k < TI1; k++) {
        red[fg][0][k][h] = a[k];
        red[fg][1][k][h] = b[k];
    }
    __syncthreads();

    if (fg == 0) {
        const float bb = b1[h];
        #pragma unroll
        for (int k = 0; k < TI1; k++) {
            float av = a[k] + red[1][0][k][h] + red[2][0][k][h] + red[3][0][k][h];
            float bv = b[k] + red[1][1][k][h] + red[2][1][k][h] + red[3][1][k][h];
            g_A[(i0 + k) * HIDDEN + h] = av + bb;
            g_B[(i0 + k) * HIDDEN + h] = bv;
        }
    }
}

// ---------------------------------------------------------------------------
// K2: separable 2D DCT -> C_jk. One block per j (NC x NQ threads).
// Double accumulation, chains split for DFMA latency.
// ---------------------------------------------------------------------------
__global__ void __launch_bounds__(NQ) k2_dct()
{
    const int j = blockIdx.x;
    const int t = threadIdx.x;

    __shared__ double Gq[NQ];

    double g0 = 0.0, g1 = 0.0, g2 = 0.0, g3 = 0.0;
    #pragma unroll
    for (int p = 0; p < NQ; p += 4) {
        g0 += (double)g_F[(p + 0) * NQ + t] * (double)g_cosT[j * NQ + p + 0];
        g1 += (double)g_F[(p + 1) * NQ + t] * (double)g_cosT[j * NQ + p + 1];
        g2 += (double)g_F[(p + 2) * NQ + t] * (double)g_cosT[j * NQ + p + 2];
        g3 += (double)g_F[(p + 3) * NQ + t] * (double)g_cosT[j * NQ + p + 3];
    }
    Gq[t] = (g0 + g1) + (g2 + g3);
    __syncthreads();

    if (t < NC) {
        double c0 = 0.0, c1 = 0.0;
        #pragma unroll
        for (int q = 0; q < NQ; q += 2) {
            c0 += Gq[q]     * (double)g_cosT[t * NQ + q];
            c1 += Gq[q + 1] * (double)g_cosT[t * NQ + q + 1];
        }
        const double wj = (j == 0) ? 1.0 : 2.0;
        const double wk = (t == 0) ? 1.0 : 2.0;
        g_C[j * NC + t] = (float)((c0 + c1) * wj * wk / ((double)NQ * NQ));
    }
}

// ---------------------------------------------------------------------------
// K3: fused moments + reduce: M_k[h] = sum_p T_k(B~[p,h]); R_j[h] = sum_k C_jk M_k[h].
// One block per h, 512 threads, 2 p's per thread, warp-shuffle reduce.
// ---------------------------------------------------------------------------
__global__ void __launch_bounds__(512) k3_moments()
{
    const int h    = blockIdx.x;
    const int t    = threadIdx.x;
    const int lane = t & 31;
    const int wid  = t >> 5;              // 16 warps
    const float invD = 1.0f / DDOM;

    float m[NC];
    #pragma unroll
    for (int k = 0; k < NC; k++) m[k] = 0.0f;

    #pragma unroll
    for (int r = 0; r < 2; r++) {
        const int p = r * 512 + t;
        float xv = g_B[p * HIDDEN + h] * invD;
        xv = fminf(fmaxf(xv, -1.0f), 1.0f);
        float tp = 1.0f, tc = xv;
        m[0] += 1.0f;
        m[1] += xv;
        const float x2 = 2.0f * xv;
        #pragma unroll
        for (int k = 2; k < NC; k++) {
            const float tn = fmaf(x2, tc, -tp);
            m[k] += tn;
            tp = tc; tc = tn;
        }
    }

    __shared__ float warp_red[16][NC];
    __shared__ float Msh[NC];

    #pragma unroll
    for (int k = 0; k < NC; k++) {
        float v = m[k];
        v += __shfl_xor_sync(0xffffffff, v, 16);
        v += __shfl_xor_sync(0xffffffff, v, 8);
        v += __shfl_xor_sync(0xffffffff, v, 4);
        v += __shfl_xor_sync(0xffffffff, v, 2);
        v += __shfl_xor_sync(0xffffffff, v, 1);
        if (lane == 0) warp_red[wid][k] = v;
    }
    __syncthreads();

    if (t < NC) {
        float s = 0.0f;
        #pragma unroll
        for (int w = 0; w < 16; w++) s += warp_red[w][t];
        Msh[t] = s;
    }
    __syncthreads();

    if (t < NC) {
        float r0 = 0.0f, r1 = 0.0f;
        #pragma unroll
        for (int k = 0; k < NC - 1; k += 2) {
            r0 = fmaf(g_C[t * NC + k],     Msh[k],     r0);
            r1 = fmaf(g_C[t * NC + k + 1], Msh[k + 1], r1);
        }
        r0 = fmaf(g_C[t * NC + NC - 1], Msh[NC - 1], r0);
        g_R[t * HIDDEN + h] = r0 + r1;
    }
}

// ---------------------------------------------------------------------------
// K4: fused main. 512 blocks x 256 threads; block covers 2 i-rows.
// Thread = (h, i): single Chebyshev recurrence; R read via __ldg inside the
// loop (R13 structure — register-preload variant spilled to local and was
// slower). Then self-term + W2 GEMV in-block.
// ---------------------------------------------------------------------------
__global__ void __launch_bounds__(2 * HIDDEN) k4_main(
    const float* __restrict__ W2, const float* __restrict__ b2,
    float* __restrict__ out)
{
    const int t  = threadIdx.x;
    const int h  = t & (HIDDEN - 1);
    const int ig = t >> 7;                // 0..1: which i-row
    const int i0 = blockIdx.x * TI4;
    const int i  = i0 + ig;
    const float invD = 1.0f / DDOM;

    __shared__ float s2[HIDDEN][TI4];     // 1 KB
    __shared__ float po[2][TI4][OUTD];    // 2 KB

    // Chebyshev evaluation: one (i,h) per thread.
    const float araw = g_A[i * HIDDEN + h];
    float a = araw * invD;
    a = fminf(fmaxf(a, -1.0f), 1.0f);
    const float x2 = 2.0f * a;
    float tp = 1.0f, tc = a;
    float s = fmaf(__ldg(&g_R[1 * HIDDEN + h]), a, __ldg(&g_R[0 * HIDDEN + h]));

    #pragma unroll
    for (int j = 2; j < NC; j++) {
        const float tn = fmaf(x2, tc, -tp);
        s = fmaf(__ldg(&g_R[j * HIDDEN + h]), tn, s);
        tp = tc; tc = tn;
    }

    // self term + scale
    const float self_t = tanh_fast(araw + g_B[i * HIDDEN + h]);
    s2[h][ig] = (s - self_t) * (1.0f / (float)(N_E - 1));
    __syncthreads();

    // GEMV through W2: 4 groups of 64 threads = (hidden half) x (i-row)
    const int o    = t & (OUTD - 1);
    const int grp  = t >> 6;              // 0..3
    const int il   = grp & 1;             // i-row
    const int half = grp >> 1;            // hidden half

    float acc = 0.0f;
    #pragma unroll 8
    for (int hh = 0; hh < HIDDEN / 2; hh++) {
        const int hid = half * (HIDDEN / 2) + hh;
        acc = fmaf(s2[hid][il], W2[hid * OUTD + o], acc);
    }
    po[half][il][o] = acc;
    __syncthreads();

    if (t < TI4 * OUTD) {
        const int oo = t & (OUTD - 1);
        const int ii = t >> 6;
        out[(i0 + ii) * OUTD + oo] = po[0][ii][oo] + po[1][ii][oo] + b2[oo];
    }
}

// ---------------------------------------------------------------------------
extern "C" void kernel_launch(void* const* d_in, const int* in_sizes, int n_in,
                              void* d_out, int out_size)
{
    // Map inputs by element count (all distinct): x=65536, W1=16384, b1=128,
    // W2=8192, b2=64.
    const float *x = nullptr, *W1 = nullptr, *b1 = nullptr, *W2 = nullptr, *b2 = nullptr;
    for (int i = 0; i < n_in; i++) {
        switch (in_sizes[i]) {
            case N_E * N_IN:          x  = (const float*)d_in[i]; break;
            case 2 * N_IN * HIDDEN:   W1 = (const float*)d_in[i]; break;
            case HIDDEN:              b1 = (const float*)d_in[i]; break;
            case HIDDEN * OUTD:       W2 = (const float*)d_in[i]; break;
            case OUTD:                b2 = (const float*)d_in[i]; break;
            default: break;
        }
    }
    float* out = (float*)d_out;

    k1_phase1_tables<<<N_E / TI1 + 2, FSPLIT * HIDDEN>>>(x, W1, b1);
    k2_dct<<<NC, NQ>>>();
    k3_moments<<<HIDDEN, 512>>>();
    k4_main<<<N_E / TI4, 2 * HIDDEN>>>(W2, b2, out);
}